// round 8
// baseline (speedup 1.0000x reference)
#include <cuda_runtime.h>
#include <cuda_bf16.h>
#include <float.h>

// VectorQuantizer: N=131072 tokens (32 x 64 x 64 NCHW), D=64, K=512.
// Outputs packed fp32: [indices 131072][quantized_st NCHW 8388608][loss 1].
//
// Bit-exact numerics (rel_err 0.0 since R3):
//   xsq  sequential rounded-mul/rounded-add; dot sequential FMA acc=0;
//   dist = fadd(fadd(xsq,-2*dot), wsq)  ==  add2(fma2(dot,-2,xsq), wsq);
//   strict-< ascending-k argmin; quantized_st = fadd(x, fsub(q,x)).
//
// R8: single fused persistent kernel (last-CTA finalize, no extra launches).
// x staged per-tile into smem via cp.async -> ~80 regs/thread -> deep LDS
// pipelining from a single warp/SMSP. 2 tokens/thread share weight LDS.
// Balance: 444 supertiles x 256 (444 = 3*148) + 136 tiles x 128.

#define NTOK      131072
#define DIM       64
#define KCODES    512
#define HW        4096
#define THREADS   128
#define GRID      148
#define NSUPER    444
#define PH2_BASE  113664
#define PH2_TILES 136
#define XSTRIDE   260          // floats; 16B-aligned rows, conflict-free

typedef unsigned long long u64;

__device__ float g_part[GRID];
__device__ int   g_ticket;     // zero-init; reset by last CTA each run

__device__ __forceinline__ u64 fma2(u64 a, u64 b, u64 c) {
    u64 d;
    asm("fma.rn.f32x2 %0, %1, %2, %3;" : "=l"(d) : "l"(a), "l"(b), "l"(c));
    return d;
}
__device__ __forceinline__ u64 add2(u64 a, u64 b) {
    u64 d;
    asm("add.rn.f32x2 %0, %1, %2;" : "=l"(d) : "l"(a), "l"(b));
    return d;
}
__device__ __forceinline__ u64 pack2(float v) {
    u64 r;
    asm("mov.b64 %0, {%1, %1};" : "=l"(r) : "f"(v));
    return r;
}
__device__ __forceinline__ void unpack2(u64 p, float& lo, float& hi) {
    asm("mov.b64 {%0, %1}, %2;" : "=f"(lo), "=f"(hi) : "l"(p));
}
__device__ __forceinline__ void cp_async16(unsigned s, const void* g) {
    asm volatile("cp.async.cg.shared.global [%0], [%1], 16;" :: "r"(s), "l"(g));
}

// Stage TOKS tokens' x into x_sm[d][tok] (tile lies within one image).
template <int TOKS>
__device__ __forceinline__ void stage_x(const float* __restrict__ in,
                                        float* x_sm, int t0) {
    const float* base = in + ((t0 >> 12) * (DIM * HW)) + (t0 & (HW - 1));
    unsigned sbase = (unsigned)__cvta_generic_to_shared(x_sm);
    constexpr int CHUNKS = TOKS * DIM / 4;      // 16B chunks
    constexpr int CPR    = TOKS / 4;            // chunks per d-row
    #pragma unroll
    for (int i = threadIdx.x; i < CHUNKS; i += THREADS) {
        int d = i / CPR, c = i % CPR;
        cp_async16(sbase + (unsigned)(d * XSTRIDE + 4 * c) * 4u,
                   base + d * HW + 4 * c);
    }
    asm volatile("cp.async.commit_group;");
    asm volatile("cp.async.wait_group 0;");
    __syncthreads();
}

// Process NT tokens (tok, tok+128) of the staged tile. Bit-exact numerics.
template <int NT>
__device__ __forceinline__ void process_tokens(
    float* __restrict__ out_idx, float* __restrict__ out_q,
    const float* wt, const float* wsq, const float* x_sm,
    int t0, float& loss_acc)
{
    int tok0 = threadIdx.x;

    // ||x||^2: sequential scalar, rounded mul then rounded add (NO fma)
    u64 xsq2[NT];
    #pragma unroll
    for (int i = 0; i < NT; i++) {
        float s = 0.f;
        #pragma unroll
        for (int d = 0; d < DIM; d++) {
            float xd = x_sm[d * XSTRIDE + tok0 + i * 128];
            s = __fadd_rn(s, __fmul_rn(xd, xd));
        }
        xsq2[i] = pack2(s);
    }

    const u64 M2 = pack2(-2.0f);
    float best[NT];
    int bestk[NT];
    #pragma unroll
    for (int i = 0; i < NT; i++) { best[i] = FLT_MAX; bestk[i] = 0; }

    for (int kb = 0; kb < KCODES; kb += 16) {
        u64 acc[NT][8];
        #pragma unroll
        for (int i = 0; i < NT; i++)
            #pragma unroll
            for (int j = 0; j < 8; j++) acc[i][j] = 0ull;

        #pragma unroll
        for (int d = 0; d < DIM; d++) {
            u64 xp[NT];
            #pragma unroll
            for (int i = 0; i < NT; i++)
                xp[i] = pack2(x_sm[d * XSTRIDE + tok0 + i * 128]);
            const ulonglong2* row =
                reinterpret_cast<const ulonglong2*>(wt + d * KCODES + kb);
            #pragma unroll
            for (int q = 0; q < 4; q++) {
                ulonglong2 wp = row[q];            // LDS.128 broadcast
                #pragma unroll
                for (int i = 0; i < NT; i++) {
                    acc[i][2 * q]     = fma2(xp[i], wp.x, acc[i][2 * q]);
                    acc[i][2 * q + 1] = fma2(xp[i], wp.y, acc[i][2 * q + 1]);
                }
            }
        }

        #pragma unroll
        for (int j = 0; j < 8; j++) {
            u64 wpair = *reinterpret_cast<const u64*>(wsq + kb + 2 * j);
            #pragma unroll
            for (int i = 0; i < NT; i++) {
                u64 dp = add2(fma2(acc[i][j], M2, xsq2[i]), wpair);
                float d0, d1;
                unpack2(dp, d0, d1);
                if (d0 < best[i]) { best[i] = d0; bestk[i] = kb + 2 * j; }
                if (d1 < best[i]) { best[i] = d1; bestk[i] = kb + 2 * j + 1; }
            }
        }
    }

    // Epilogue: straight-through output + loss partial.
    #pragma unroll
    for (int i = 0; i < NT; i++) {
        int t = t0 + tok0 + i * 128;
        float* pq = out_q + ((t >> 12) * (DIM * HW)) + (t & (HW - 1));
        #pragma unroll
        for (int d = 0; d < DIM; d++) {
            float xd = x_sm[d * XSTRIDE + tok0 + i * 128];
            float qv = wt[d * KCODES + bestk[i]];
            float e  = __fsub_rn(qv, xd);          // q - x (one rounding)
            pq[d * HW] = __fadd_rn(xd, e);         // x + (q - x)
            loss_acc = fmaf(e, e, loss_acc);
        }
        out_idx[t] = (float)bestk[i];
    }
    __syncthreads();   // x_sm reused by next tile
}

__global__ __launch_bounds__(THREADS, 1) void vq_main(
    const float* __restrict__ in,   // [32, 64, 64, 64] NCHW
    const float* __restrict__ w,    // [512, 64]
    float* __restrict__ out_idx,    // [131072]
    float* __restrict__ out_q,      // [32, 64, 64, 64] NCHW
    float* __restrict__ out_loss)   // [1]
{
    extern __shared__ float sm[];
    float* wt   = sm;                         // [64][512]
    float* wsq  = sm + DIM * KCODES;          // [512]
    float* red  = wsq + KCODES;               // [8]
    float* x_sm = red + 8;                    // [64][XSTRIDE]

    for (int e = threadIdx.x; e < KCODES * DIM; e += THREADS) {
        int k = e >> 6, d = e & 63;
        wt[d * KCODES + k] = w[e];
    }
    __syncthreads();

    for (int k = threadIdx.x; k < KCODES; k += THREADS) {
        float s = 0.f;
        for (int d = 0; d < DIM; d++) {
            float v = wt[d * KCODES + k];
            s = __fadd_rn(s, __fmul_rn(v, v));
        }
        wsq[k] = s;
    }
    __syncthreads();

    float loss_acc = 0.f;

    // Phase 1: 444 supertiles of 256 tokens, 2 tokens/thread.
    for (int st = blockIdx.x; st < NSUPER; st += GRID) {
        int t0 = st * 256;
        stage_x<256>(in, x_sm, t0);
        process_tokens<2>(out_idx, out_q, wt, wsq, x_sm, t0, loss_acc);
    }
    // Phase 2: 136 tiles of 128 tokens, 1 token/thread.
    for (int tile = blockIdx.x; tile < PH2_TILES; tile += GRID) {
        int t0 = PH2_BASE + tile * 128;
        stage_x<128>(in, x_sm, t0);
        process_tokens<1>(out_idx, out_q, wt, wsq, x_sm, t0, loss_acc);
    }

    // Per-CTA deterministic loss partial
    #pragma unroll
    for (int o = 16; o > 0; o >>= 1)
        loss_acc += __shfl_xor_sync(0xffffffffu, loss_acc, o);
    int wid = threadIdx.x >> 5, lid = threadIdx.x & 31;
    if (lid == 0) red[wid] = loss_acc;
    __syncthreads();
    if (threadIdx.x == 0) {
        double s = 0.0;
        for (int i = 0; i < THREADS / 32; i++) s += (double)red[i];
        g_part[blockIdx.x] = (float)s;
    }

    // Last-CTA finalize (deterministic fixed-tree sum of 148 partials).
    if (threadIdx.x == 0) {
        __threadfence();
        int ticket = atomicAdd(&g_ticket, 1);
        red[4] = (ticket == GRID - 1) ? 1.f : 0.f;
    }
    __syncthreads();
    if (red[4] != 0.f) {
        __threadfence();
        int tid = threadIdx.x;
        double v = (tid < GRID) ? (double)g_part[tid] : 0.0;
        if (tid + 128 < GRID) v += (double)g_part[tid + 128];
        #pragma unroll
        for (int o = 16; o > 0; o >>= 1)
            v += __shfl_xor_sync(0xffffffffu, v, o);
        __shared__ double wr[4];
        if (lid == 0) wr[wid] = v;
        __syncthreads();
        if (tid == 0) {
            double s = wr[0] + wr[1] + wr[2] + wr[3];
            out_loss[0] = (float)(s * (1.25 / 8388608.0));
            g_ticket = 0;          // reset for next graph replay
            __threadfence();
        }
    }
}

extern "C" void kernel_launch(void* const* d_in, const int* in_sizes, int n_in,
                              void* d_out, int out_size) {
    const float* in = (const float*)d_in[0];
    const float* w  = (const float*)d_in[1];
    float* out      = (float*)d_out;

    float* out_idx  = out;
    float* out_q    = out + NTOK;
    float* out_loss = out + NTOK + NTOK * DIM;

    int smem = (DIM * KCODES + KCODES + 8 + DIM * XSTRIDE) * (int)sizeof(float);
    cudaFuncSetAttribute(vq_main, cudaFuncAttributeMaxDynamicSharedMemorySize, smem);
    vq_main<<<GRID, THREADS, smem>>>(in, w, out_idx, out_q, out_loss);
}